// round 1
// baseline (speedup 1.0000x reference)
#include <cuda_runtime.h>
#include <math.h>

#define RCR 5.2f
#define RCA 3.5f
#define NSP 4
#define NATOMS 32
#define NSHFR 16
#define NSHFA 4
#define NSHFZ 8
#define NPAIRBIN 10
#define RAD_FEAT (NSP*NSHFR)            /* 64  */
#define ANG_FEAT (NPAIRBIN*NSHFA*NSHFZ) /* 320 */
#define OUT_FEAT (RAD_FEAT+ANG_FEAT)    /* 384 */
#define WARPS 4

__global__ __launch_bounds__(128) void aev_kernel(
    const float* __restrict__ coords,
    const float* __restrict__ etaR_p,
    const float* __restrict__ shfR_p,
    const float* __restrict__ etaA_p,
    const float* __restrict__ zeta_p,
    const float* __restrict__ shfA_p,
    const float* __restrict__ shfZ_p,
    const int*   __restrict__ species,
    float* __restrict__ out)
{
    __shared__ float s_cx[NATOMS], s_cy[NATOMS], s_cz[NATOMS];
    __shared__ int   s_sp[NATOMS];
    __shared__ float s_shfR[NSHFR], s_shfA[NSHFA];
    __shared__ float s_cosZ[NSHFZ], s_sinZ[NSHFZ];
    __shared__ float s_nbvx[WARPS][NATOMS], s_nbvy[WARPS][NATOMS], s_nbvz[WARPS][NATOMS];
    __shared__ float s_nbd[WARPS][NATOMS], s_nbfc[WARPS][NATOMS];
    __shared__ int   s_nbsp[WARPS][NATOMS];
    __shared__ float s_acc[WARPS][OUT_FEAT];
    __shared__ float s_etaR, s_etaA, s_zeta;

    const int tid  = threadIdx.x;
    const int warp = tid >> 5;
    const int lane = tid & 31;
    const int b    = blockIdx.x >> 3;               // 8 blocks per molecule
    const int i    = ((blockIdx.x & 7) << 2) + warp; // atom handled by this warp

    // ---- block-wide loads ----
    if (tid < NATOMS) {
        s_cx[tid] = coords[(b*NATOMS + tid)*3 + 0];
        s_cy[tid] = coords[(b*NATOMS + tid)*3 + 1];
        s_cz[tid] = coords[(b*NATOMS + tid)*3 + 2];
        s_sp[tid] = species[b*NATOMS + tid];
    }
    if (tid >= 32 && tid < 32 + NSHFR) s_shfR[tid-32] = shfR_p[tid-32];
    if (tid >= 64 && tid < 64 + NSHFA) s_shfA[tid-64] = shfA_p[tid-64];
    if (tid >= 96 && tid < 96 + NSHFZ) {
        float z = shfZ_p[tid-96];
        s_cosZ[tid-96] = cosf(z);
        s_sinZ[tid-96] = sinf(z);
    }
    if (tid == 0) { s_etaR = etaR_p[0]; s_etaA = etaA_p[0]; s_zeta = zeta_p[0]; }

    for (int f = tid; f < WARPS*OUT_FEAT; f += blockDim.x)
        (&s_acc[0][0])[f] = 0.0f;
    __syncthreads();

    // ---- per-warp: atom i ----
    const float cix = s_cx[i], ciy = s_cy[i], ciz = s_cz[i];
    const int   spi = s_sp[i];
    const bool  valid_i = (spi >= 0);

    // lane <-> candidate neighbor j = lane
    float vx = s_cx[lane] - cix;
    float vy = s_cy[lane] - ciy;
    float vz = s_cz[lane] - ciz;
    float d2 = vx*vx + vy*vy + vz*vz;
    float d  = sqrtf(d2 > 0.0f ? d2 : 1.0f);
    int   spl = s_sp[lane];
    bool  valid_l = (spl >= 0);
    int   spc = min(max(spl, 0), NSP-1);
    bool  pair_ok = valid_i && valid_l && (lane != i);

    const float etaR = s_etaR, etaA = s_etaA, zeta = s_zeta;
    const float PI_RCR = 3.14159265358979323846f / RCR;
    const float PI_RCA = 3.14159265358979323846f / RCA;

    // ---- radial: lane j accumulates its 16 shifts into shared via atomics ----
    if (pair_ok && d <= RCR) {
        float fcR  = 0.5f*cosf(d*PI_RCR) + 0.5f;
        float base = 0.25f*fcR;
        float* rad = &s_acc[warp][spc*NSHFR];
        #pragma unroll
        for (int r = 0; r < NSHFR; r++) {
            float e = d - s_shfR[r];
            atomicAdd(&rad[r], base*expf(-etaR*e*e));
        }
    }

    // ---- angular: warp-compacted neighbor list ----
    bool isnb = pair_ok && (d <= RCA);
    unsigned m = __ballot_sync(0xffffffffu, isnb);
    int nc = __popc(m);
    if (isnb) {
        int pos = __popc(m & ((1u << lane) - 1u));
        s_nbvx[warp][pos] = vx;
        s_nbvy[warp][pos] = vy;
        s_nbvz[warp][pos] = vz;
        s_nbd [warp][pos] = d;
        s_nbfc[warp][pos] = 0.5f*cosf(d*PI_RCA) + 0.5f;
        s_nbsp[warp][pos] = spc;
    }
    __syncwarp();

    // lane owns angular feature f = p*8 + t  (p: ShfA idx, t: ShfZ idx)
    const float shfA_l = s_shfA[lane >> 3];
    const float cZ = s_cosZ[lane & 7];
    const float sZ = s_sinZ[lane & 7];
    const bool  z32 = fabsf(zeta - 32.0f) < 1e-4f;
    float* accA = &s_acc[warp][RAD_FEAT];

    for (int a = 0; a < nc - 1; a++) {
        float ax = s_nbvx[warp][a], ay = s_nbvy[warp][a], az = s_nbvz[warp][a];
        float da = s_nbd[warp][a],  fa = s_nbfc[warp][a];
        int   sa = s_nbsp[warp][a];
        for (int q = a + 1; q < nc; q++) {
            float bx = s_nbvx[warp][q], by = s_nbvy[warp][q], bz = s_nbvz[warp][q];
            float db = s_nbd[warp][q],  fb = s_nbfc[warp][q];
            int   sb = s_nbsp[warp][q];

            float dot = ax*bx + ay*by + az*bz;
            float c   = 0.95f * (dot / fmaxf(da*db, 1e-10f));
            float st  = sqrtf(fmaxf(1.0f - c*c, 0.0f));  // sin(arccos(c)) >= 0
            float dmean = 0.5f*(da + db);
            float w   = 2.0f*fa*fb;   // 0.5 * (2 ordered orientations) * 2.0 factor

            int lo = min(sa, sb), hi = max(sa, sb);
            int pbin = lo*NSP - ((lo*(lo-1)) >> 1) + (hi - lo);

            // cos(theta - ShfZ[t]) without acos
            float cosd = c*cZ + st*sZ;
            float x = fmaxf(0.5f + 0.5f*cosd, 0.0f);
            float f1;
            if (z32) {
                float x2 = x*x, x4 = x2*x2, x8 = x4*x4, x16 = x8*x8;
                f1 = x16*x16;
            } else {
                f1 = powf(x, zeta);
            }
            float e  = dmean - shfA_l;
            float f2 = expf(-etaA*e*e);

            accA[pbin*32 + lane] += w*f1*f2;
        }
    }
    __syncwarp();

    // ---- write 384 features for atom i ----
    float* op = out + (size_t)(b*NATOMS + i)*OUT_FEAT;
    #pragma unroll
    for (int f = lane; f < OUT_FEAT; f += 32)
        op[f] = s_acc[warp][f];
}

extern "C" void kernel_launch(void* const* d_in, const int* in_sizes, int n_in,
                              void* d_out, int out_size)
{
    const float* coords = (const float*)d_in[0];
    const float* etaR   = (const float*)d_in[1];
    const float* shfR   = (const float*)d_in[2];
    const float* etaA   = (const float*)d_in[3];
    const float* zeta   = (const float*)d_in[4];
    const float* shfA   = (const float*)d_in[5];
    const float* shfZ   = (const float*)d_in[6];
    const int*   spec   = (const int*)d_in[7];
    float* out = (float*)d_out;

    int B = in_sizes[0] / (NATOMS*3);
    dim3 grid(B * (NATOMS/4));  // 4 atoms (warps) per block
    aev_kernel<<<grid, 128>>>(coords, etaR, shfR, etaA, zeta, shfA, shfZ, spec, out);
}

// round 2
// speedup vs baseline: 2.2532x; 2.2532x over previous
#include <cuda_runtime.h>
#include <math.h>

#define RCR 5.2f
#define RCA 3.5f
#define NSP 4
#define NATOMS 32
#define NSHFR 16
#define NSHFA 4
#define NSHFZ 8
#define NPAIRBIN 10
#define RAD_FEAT (NSP*NSHFR)            /* 64  */
#define ANG_FEAT (NPAIRBIN*NSHFA*NSHFZ) /* 320 */
#define OUT_FEAT (RAD_FEAT+ANG_FEAT)    /* 384 */
#define WARPS 2
#define LOG2E 1.4426950408889634f
#define SQRT095 0.97467943448089633f

__device__ __forceinline__ float ex2f(float x){ float y; asm("ex2.approx.ftz.f32 %0, %1;":"=f"(y):"f"(x)); return y; }
__device__ __forceinline__ float sqrt_apx(float x){ float y; asm("sqrt.approx.ftz.f32 %0, %1;":"=f"(y):"f"(x)); return y; }
__device__ __forceinline__ float rsqrt_apx(float x){ float y; asm("rsqrt.approx.ftz.f32 %0, %1;":"=f"(y):"f"(x)); return y; }

// Angular accumulation over species-sorted neighbor list.
// Each lane owns angular feature f = p*8 + t (p = ShfA idx, t = ShfZ idx).
template<bool Z32>
__device__ __forceinline__ void angular_loop(
    const float4* __restrict__ l4, const float2* __restrict__ l2,
    const int* __restrict__ off, int ncA, int lane,
    float shfA_l, float cZ, float sZ, float nEtaA, float zeta,
    float* __restrict__ accA)
{
    int sa = 0;
    for (int a = 0; a < ncA - 1; a++) {
        while (a >= off[sa + 1]) sa++;
        float4 A4 = l4[a];
        float2 A2 = l2[a];
        // fold inva*sqrt(0.95) into the a-side vector
        float ax = A4.x * A4.w, ay = A4.y * A4.w, az = A4.z * A4.w;
        float ea  = A2.x - shfA_l;   // 0.5*da - ShfA[p]
        float fa2 = 2.0f * A2.y;     // 2*fcA(da)
        int pbin0 = sa * NSP - ((sa * (sa - 1)) >> 1);
        #pragma unroll
        for (int sb = 0; sb < NSP; sb++) {
            if (sb < sa) continue;
            int q0 = off[sb]; if (a + 1 > q0) q0 = a + 1;
            int q1 = off[sb + 1];
            if (q0 >= q1) continue;
            float r = 0.0f;
            for (int q = q0; q < q1; q++) {
                float4 B4 = l4[q];
                float2 B2 = l2[q];
                float dot = ax * B4.x + ay * B4.y + az * B4.z;
                float c   = dot * B4.w;                      // 0.95 * cos(theta)
                float st  = sqrt_apx(fmaxf(1.0f - c * c, 0.0f)); // sin >= 0
                float cosd = fmaf(c, cZ, st * sZ);           // cos(theta - ShfZ[t])
                float x    = fmaf(cosd, 0.5f, 0.5f);         // in [0,1]
                float f1;
                if (Z32) { float x2=x*x, x4=x2*x2, x8=x4*x4, x16=x8*x8; f1 = x16*x16; }
                else     { f1 = __powf(x, zeta); }
                float e  = ea + B2.x;                        // dmean - ShfA[p]
                float f2 = ex2f(nEtaA * (e * e));            // exp(-etaA*e^2)
                float w  = fa2 * B2.y;                       // 2*fcA(da)*fcA(db)
                r = fmaf(w * f1, f2, r);
            }
            int pbin = pbin0 + (sb - sa);
            accA[pbin * 32 + lane] += r;
        }
    }
}

__global__ __launch_bounds__(WARPS*32) void aev_kernel(
    const float* __restrict__ coords,
    const float* __restrict__ etaR_p,
    const float* __restrict__ shfR_p,
    const float* __restrict__ etaA_p,
    const float* __restrict__ zeta_p,
    const float* __restrict__ shfA_p,
    const float* __restrict__ shfZ_p,
    const int*   __restrict__ species,
    float* __restrict__ out)
{
    __shared__ float s_cx[NATOMS], s_cy[NATOMS], s_cz[NATOMS];
    __shared__ int   s_sp[NATOMS];
    __shared__ float s_shfR[NSHFR], s_shfA[NSHFA];
    __shared__ float s_cosZ[NSHFZ], s_sinZ[NSHFZ];
    __shared__ float4 s_l4[WARPS][NATOMS];
    __shared__ float2 s_l2[WARPS][NATOMS];
    __shared__ int    s_off[WARPS][NSP + 1];
    __shared__ float  s_acc[WARPS][OUT_FEAT];
    __shared__ float  s_etaR, s_etaA, s_zeta;

    const int tid  = threadIdx.x;
    const int warp = tid >> 5;
    const int lane = tid & 31;
    const int b    = blockIdx.x >> 4;                       // 16 blocks per molecule
    const int i    = ((blockIdx.x & 15) << 1) + warp;       // atom for this warp

    // ---- block-wide loads (64 threads) ----
    if (tid < NATOMS) {
        s_cx[tid] = coords[(b*NATOMS + tid)*3 + 0];
        s_cy[tid] = coords[(b*NATOMS + tid)*3 + 1];
        s_cz[tid] = coords[(b*NATOMS + tid)*3 + 2];
        s_sp[tid] = species[b*NATOMS + tid];
    } else if (tid < 32 + NSHFR) {
        s_shfR[tid-32] = shfR_p[tid-32];
    } else if (tid < 48 + NSHFA) {
        s_shfA[tid-48] = shfA_p[tid-48];
    } else if (tid < 52 + 3) {
        if (tid == 52) s_etaR = etaR_p[0];
        if (tid == 53) s_etaA = etaA_p[0];
        if (tid == 54) s_zeta = zeta_p[0];
    } else if (tid >= 56) {
        float z = shfZ_p[tid-56];
        s_cosZ[tid-56] = cosf(z);
        s_sinZ[tid-56] = sinf(z);
    }
    for (int f = tid; f < WARPS*OUT_FEAT; f += blockDim.x)
        (&s_acc[0][0])[f] = 0.0f;
    __syncthreads();

    const float etaR = s_etaR, etaA = s_etaA, zeta = s_zeta;
    const float nEtaR = -etaR * LOG2E;
    const float nEtaA = -etaA * LOG2E;
    const float PI_RCR = 3.14159265358979323846f / RCR;
    const float PI_RCA = 3.14159265358979323846f / RCA;

    // ---- per-warp: atom i; candidate neighbor j = lane ----
    const float cix = s_cx[i], ciy = s_cy[i], ciz = s_cz[i];
    const bool  valid_i = (s_sp[i] >= 0);

    float vx = s_cx[lane] - cix;
    float vy = s_cy[lane] - ciy;
    float vz = s_cz[lane] - ciz;
    float d2 = vx*vx + vy*vy + vz*vz;
    float inv = rsqrt_apx(fmaxf(d2, 1e-24f));
    float d   = d2 * inv;
    int   spl = s_sp[lane];
    int   spc = min(max(spl, 0), NSP-1);
    bool  pair_ok = valid_i && (spl >= 0) && (lane != i);

    // ---- radial: staggered shared atomics (<=2-way address conflicts) ----
    if (pair_ok && d <= RCR) {
        float fcR  = fmaf(0.5f, __cosf(d * PI_RCR), 0.5f);
        float base = 0.25f * fcR;
        float* rad = &s_acc[warp][spc * NSHFR];
        int r0 = lane & 15;
        #pragma unroll
        for (int k = 0; k < NSHFR; k++) {
            int r = (r0 + k) & 15;
            float e = d - s_shfR[r];
            atomicAdd(&rad[r], base * ex2f(nEtaR * (e * e)));
        }
    }

    // ---- angular: species-sorted warp-compacted neighbor list ----
    bool isnb = pair_ok && (d <= RCA);
    unsigned ms[NSP];
    #pragma unroll
    for (int s = 0; s < NSP; s++)
        ms[s] = __ballot_sync(0xffffffffu, isnb && (spc == s));

    int off0 = 0;
    int off1 = off0 + __popc(ms[0]);
    int off2 = off1 + __popc(ms[1]);
    int off3 = off2 + __popc(ms[2]);
    int ncA  = off3 + __popc(ms[3]);
    if (lane == 0) {
        s_off[warp][0] = 0;   s_off[warp][1] = off1;
        s_off[warp][2] = off2; s_off[warp][3] = off3;
        s_off[warp][4] = ncA;
    }
    if (isnb) {
        unsigned lt = (1u << lane) - 1u;
        int base = (spc == 0) ? off0 : (spc == 1) ? off1 : (spc == 2) ? off2 : off3;
        int pos = base + __popc(ms[spc] & lt);
        float fcA = fmaf(0.5f, __cosf(d * PI_RCA), 0.5f);
        s_l4[warp][pos] = make_float4(vx, vy, vz, inv * SQRT095);
        s_l2[warp][pos] = make_float2(0.5f * d, fcA);
    }
    __syncwarp();

    const float shfA_l = s_shfA[lane >> 3];
    const float cZ = s_cosZ[lane & 7];
    const float sZ = s_sinZ[lane & 7];
    float* accA = &s_acc[warp][RAD_FEAT];

    if (fabsf(zeta - 32.0f) < 1e-4f)
        angular_loop<true >(s_l4[warp], s_l2[warp], s_off[warp], ncA, lane,
                            shfA_l, cZ, sZ, nEtaA, zeta, accA);
    else
        angular_loop<false>(s_l4[warp], s_l2[warp], s_off[warp], ncA, lane,
                            shfA_l, cZ, sZ, nEtaA, zeta, accA);
    __syncwarp();

    // ---- write 384 features for atom i ----
    float* op = out + (size_t)(b*NATOMS + i) * OUT_FEAT;
    #pragma unroll
    for (int f = lane; f < OUT_FEAT; f += 32)
        op[f] = s_acc[warp][f];
}

extern "C" void kernel_launch(void* const* d_in, const int* in_sizes, int n_in,
                              void* d_out, int out_size)
{
    const float* coords = (const float*)d_in[0];
    const float* etaR   = (const float*)d_in[1];
    const float* shfR   = (const float*)d_in[2];
    const float* etaA   = (const float*)d_in[3];
    const float* zeta   = (const float*)d_in[4];
    const float* shfA   = (const float*)d_in[5];
    const float* shfZ   = (const float*)d_in[6];
    const int*   spec   = (const int*)d_in[7];
    float* out = (float*)d_out;

    int B = in_sizes[0] / (NATOMS*3);
    dim3 grid(B * (NATOMS/WARPS));   // 2 atoms (warps) per 64-thread block
    aev_kernel<<<grid, WARPS*32>>>(coords, etaR, shfR, etaA, zeta, shfA, shfZ, spec, out);
}

// round 3
// speedup vs baseline: 3.0439x; 1.3509x over previous
#include <cuda_runtime.h>
#include <math.h>

#define RCR 5.2f
#define RCA 3.5f
#define NSP 4
#define NATOMS 32
#define NSHFR 16
#define NSHFA 4
#define NSHFZ 8
#define NPAIRBIN 10
#define RAD_FEAT (NSP*NSHFR)            /* 64  */
#define ANG_FEAT (NPAIRBIN*NSHFA*NSHFZ) /* 320 */
#define OUT_FEAT (RAD_FEAT+ANG_FEAT)    /* 384 */
#define LOG2E 1.4426950408889634f
#define SQRT095 0.97467943448089633f

__device__ __forceinline__ float ex2f(float x){ float y; asm("ex2.approx.ftz.f32 %0, %1;":"=f"(y):"f"(x)); return y; }
__device__ __forceinline__ float sqrt_apx(float x){ float y; asm("sqrt.approx.ftz.f32 %0, %1;":"=f"(y):"f"(x)); return y; }
__device__ __forceinline__ float rsqrt_apx(float x){ float y; asm("rsqrt.approx.ftz.f32 %0, %1;":"=f"(y):"f"(x)); return y; }

// Angular accumulation: this warp takes outer indices a = parity, parity+2, ...
// Lane owns angular feature f = p*8 + t (p = ShfA idx, t = ShfZ idx).
template<bool Z32>
__device__ __forceinline__ void angular_loop(
    const float4* __restrict__ l4, const float2* __restrict__ l2,
    int o1, int o2, int o3, int ncA, int parity, int lane,
    float shfA_l, float cZ, float sZ, float nEtaA, float zeta,
    float* __restrict__ accA)
{
    for (int a = parity; a < ncA - 1; a += 2) {
        // species group of a (branchless; boundaries in registers)
        int sa = (a >= o3) ? 3 : (a >= o2) ? 2 : (a >= o1) ? 1 : 0;
        float4 A4 = l4[a];
        float2 A2 = l2[a];
        float ax = A4.x * A4.w, ay = A4.y * A4.w, az = A4.z * A4.w;
        float ea  = A2.x - shfA_l;   // 0.5*da - ShfA[p]
        float fa2 = 2.0f * A2.y;     // 2*fcA(da)
        int pbin0 = sa * NSP - ((sa * (sa - 1)) >> 1);
        #pragma unroll
        for (int sb = 0; sb < NSP; sb++) {
            int gq0 = (sb == 0) ? 0  : (sb == 1) ? o1 : (sb == 2) ? o2 : o3;
            int gq1 = (sb == 0) ? o1 : (sb == 1) ? o2 : (sb == 2) ? o3 : ncA;
            if (sb < sa) continue;
            int q0 = (a + 1 > gq0) ? a + 1 : gq0;
            if (q0 >= gq1) continue;
            float r = 0.0f;
            #pragma unroll 2
            for (int q = q0; q < gq1; q++) {
                float4 B4 = l4[q];
                float2 B2 = l2[q];
                float dot = ax * B4.x + ay * B4.y + az * B4.z;
                float c   = dot * B4.w;                  // 0.95*cos(theta), |c|<=0.951
                float st  = sqrt_apx(1.0f - c * c);      // >= 0.097, no clamp needed
                float cosd = fmaf(c, cZ, st * sZ);       // cos(theta - ShfZ[t])
                float x    = fmaf(cosd, 0.5f, 0.5f);
                float f1;
                if (Z32) { float x2=x*x, x4=x2*x2, x8=x4*x4, x16=x8*x8; f1 = x16*x16; }
                else     { f1 = __powf(x, zeta); }
                float e  = ea + B2.x;                    // dmean - ShfA[p]
                float f2 = ex2f(nEtaA * (e * e));        // exp(-etaA*e^2)
                float wf1 = (fa2 * B2.y) * f1;
                r = fmaf(wf1, f2, r);
            }
            accA[(pbin0 + (sb - sa)) * 32 + lane] += r;
        }
    }
}

__global__ __launch_bounds__(128) void aev_kernel(
    const float* __restrict__ coords,
    const float* __restrict__ etaR_p,
    const float* __restrict__ shfR_p,
    const float* __restrict__ etaA_p,
    const float* __restrict__ zeta_p,
    const float* __restrict__ shfA_p,
    const float* __restrict__ shfZ_p,
    const int*   __restrict__ species,
    float* __restrict__ out)
{
    __shared__ float s_cx[NATOMS], s_cy[NATOMS], s_cz[NATOMS];
    __shared__ int   s_sp[NATOMS];
    __shared__ float s_shfR[NSHFR], s_shfA[NSHFA];
    __shared__ float s_cosZ[NSHFZ], s_sinZ[NSHFZ];
    __shared__ float4 s_l4[2][NATOMS];       // per atom-slot
    __shared__ float2 s_l2[2][NATOMS];
    __shared__ float  s_acc[4][OUT_FEAT];    // per warp
    __shared__ float  s_etaR, s_etaA, s_zeta;

    const int tid    = threadIdx.x;
    const int warp   = tid >> 5;
    const int lane   = tid & 31;
    const int slot   = warp >> 1;            // which of the 2 atoms in this block
    const int parity = warp & 1;             // which half of the pair loop
    const int b      = blockIdx.x >> 4;      // 16 blocks per molecule
    const int i      = ((blockIdx.x & 15) << 1) + slot;

    // ---- block-wide loads ----
    if (tid < NATOMS) {
        s_cx[tid] = coords[(b*NATOMS + tid)*3 + 0];
        s_cy[tid] = coords[(b*NATOMS + tid)*3 + 1];
        s_cz[tid] = coords[(b*NATOMS + tid)*3 + 2];
        s_sp[tid] = species[b*NATOMS + tid];
    } else if (tid < 32 + NSHFR) {
        s_shfR[tid-32] = shfR_p[tid-32];
    } else if (tid < 48 + NSHFA) {
        s_shfA[tid-48] = shfA_p[tid-48];
    } else if (tid < 55) {
        if (tid == 52) s_etaR = etaR_p[0];
        if (tid == 53) s_etaA = etaA_p[0];
        if (tid == 54) s_zeta = zeta_p[0];
    } else if (tid >= 56 && tid < 64) {
        float z = shfZ_p[tid-56];
        s_cosZ[tid-56] = cosf(z);
        s_sinZ[tid-56] = sinf(z);
    }
    for (int f = tid; f < 4*OUT_FEAT; f += blockDim.x)
        (&s_acc[0][0])[f] = 0.0f;
    __syncthreads();

    const float etaR = s_etaR, etaA = s_etaA, zeta = s_zeta;
    const float nEtaR = -etaR * LOG2E;
    const float nEtaA = -etaA * LOG2E;
    const float PI_RCR = 3.14159265358979323846f / RCR;
    const float PI_RCA = 3.14159265358979323846f / RCA;

    // ---- per-warp: atom i; candidate neighbor j = lane ----
    const float cix = s_cx[i], ciy = s_cy[i], ciz = s_cz[i];
    const bool  valid_i = (s_sp[i] >= 0);

    float vx = s_cx[lane] - cix;
    float vy = s_cy[lane] - ciy;
    float vz = s_cz[lane] - ciz;
    float d2 = vx*vx + vy*vy + vz*vz;
    float inv = rsqrt_apx(fmaxf(d2, 1e-24f));
    float d   = d2 * inv;
    int   spl = s_sp[lane];
    int   spc = min(max(spl, 0), NSP-1);
    bool  pair_ok = valid_i && (spl >= 0) && (lane != i);

    // ---- radial: 8 shifts per warp of the pair, staggered atomics ----
    if (pair_ok && d <= RCR) {
        float fcR  = fmaf(0.5f, __cosf(d * PI_RCR), 0.5f);
        float base = 0.25f * fcR;
        float* rad = &s_acc[warp][spc * NSHFR];
        int r0 = lane & 15;
        #pragma unroll
        for (int k = parity*8; k < parity*8 + 8; k++) {
            int r = (r0 + k) & 15;
            float e = d - s_shfR[r];
            atomicAdd(&rad[r], base * ex2f(nEtaR * (e * e)));
        }
    }

    // ---- angular: species-sorted compacted list (both warps compute ballots;
    //      parity 0 writes the shared copy) ----
    bool isnb = pair_ok && (d <= RCA);
    unsigned ms[NSP];
    #pragma unroll
    for (int s = 0; s < NSP; s++)
        ms[s] = __ballot_sync(0xffffffffu, isnb && (spc == s));

    int o1 = __popc(ms[0]);
    int o2 = o1 + __popc(ms[1]);
    int o3 = o2 + __popc(ms[2]);
    int ncA = o3 + __popc(ms[3]);

    if (parity == 0 && isnb) {
        unsigned lt = (1u << lane) - 1u;
        int base = (spc == 0) ? 0 : (spc == 1) ? o1 : (spc == 2) ? o2 : o3;
        int pos = base + __popc(ms[spc] & lt);
        float fcA = fmaf(0.5f, __cosf(d * PI_RCA), 0.5f);
        s_l4[slot][pos] = make_float4(vx, vy, vz, inv * SQRT095);
        s_l2[slot][pos] = make_float2(0.5f * d, fcA);
    }
    __syncthreads();

    const float shfA_l = s_shfA[lane >> 3];
    const float cZ = s_cosZ[lane & 7];
    const float sZ = s_sinZ[lane & 7];
    float* accA = &s_acc[warp][RAD_FEAT];

    if (fabsf(zeta - 32.0f) < 1e-4f)
        angular_loop<true >(s_l4[slot], s_l2[slot], o1, o2, o3, ncA, parity, lane,
                            shfA_l, cZ, sZ, nEtaA, zeta, accA);
    else
        angular_loop<false>(s_l4[slot], s_l2[slot], o1, o2, o3, ncA, parity, lane,
                            shfA_l, cZ, sZ, nEtaA, zeta, accA);
    __syncthreads();

    // ---- write: sum the two warp banks; each warp writes half the features ----
    float* op = out + (size_t)(b*NATOMS + i) * OUT_FEAT;
    const float* a0 = s_acc[slot*2 + 0];
    const float* a1 = s_acc[slot*2 + 1];
    #pragma unroll
    for (int f = parity*192 + lane; f < parity*192 + 192; f += 32)
        op[f] = a0[f] + a1[f];
}

extern "C" void kernel_launch(void* const* d_in, const int* in_sizes, int n_in,
                              void* d_out, int out_size)
{
    const float* coords = (const float*)d_in[0];
    const float* etaR   = (const float*)d_in[1];
    const float* shfR   = (const float*)d_in[2];
    const float* etaA   = (const float*)d_in[3];
    const float* zeta   = (const float*)d_in[4];
    const float* shfA   = (const float*)d_in[5];
    const float* shfZ   = (const float*)d_in[6];
    const int*   spec   = (const int*)d_in[7];
    float* out = (float*)d_out;

    int B = in_sizes[0] / (NATOMS*3);
    dim3 grid(B * 16);   // 2 atoms per block, 2 warps per atom
    aev_kernel<<<grid, 128>>>(coords, etaR, shfR, etaA, zeta, shfA, shfZ, spec, out);
}

// round 4
// speedup vs baseline: 3.2736x; 1.0755x over previous
#include <cuda_runtime.h>
#include <math.h>

#define RCR 5.2f
#define RCA 3.5f
#define NSP 4
#define NATOMS 32
#define NSHFR 16
#define NSHFA 4
#define NSHFZ 8
#define NPAIRBIN 10
#define RAD_FEAT (NSP*NSHFR)            /* 64  */
#define ANG_FEAT (NPAIRBIN*NSHFA*NSHFZ) /* 320 */
#define OUT_FEAT (RAD_FEAT+ANG_FEAT)    /* 384 */
#define AWARPS 4                         /* warps per atom */
#define LOG2E 1.4426950408889634f
#define SQRT095 0.97467943448089633f

__device__ __forceinline__ float ex2f(float x){ float y; asm("ex2.approx.ftz.f32 %0, %1;":"=f"(y):"f"(x)); return y; }
__device__ __forceinline__ float sqrt_apx(float x){ float y; asm("sqrt.approx.ftz.f32 %0, %1;":"=f"(y):"f"(x)); return y; }
__device__ __forceinline__ float rsqrt_apx(float x){ float y; asm("rsqrt.approx.ftz.f32 %0, %1;":"=f"(y):"f"(x)); return y; }

// Angular: this warp takes outer indices a = parity, parity+4, ...
// Lane owns angular feature f = p*8 + t (p = ShfA idx, t = ShfZ idx).
template<bool Z32>
__device__ __forceinline__ void angular_loop(
    const float4* __restrict__ l4, const float4* __restrict__ lb,
    int o1, int o2, int o3, int ncA, int parity, int lane,
    float shfA_l, float cZ, float sZ, float nEtaA, float zeta,
    float* __restrict__ accA)
{
    const float nEtaA2 = 2.0f * nEtaA;
    for (int a = parity; a < ncA - 1; a += AWARPS) {
        int sa = (a >= o3) ? 3 : (a >= o2) ? 2 : (a >= o1) ? 1 : 0;
        float4 A4 = l4[a];
        float4 AB = lb[a];
        float ax = A4.x * A4.w, ay = A4.y * A4.w, az = A4.z * A4.w;
        float ea  = AB.x - shfA_l;       // 0.5*da - ShfA[p]
        float k1  = nEtaA * ea * ea;     // per-a Gaussian pieces
        float k2  = nEtaA2 * ea;
        float fa2 = 2.0f * AB.y;         // 2*fcA(da)
        int pbin0 = sa * NSP - ((sa * (sa - 1)) >> 1);
        #pragma unroll
        for (int sb = 0; sb < NSP; sb++) {
            int gq0 = (sb == 0) ? 0  : (sb == 1) ? o1 : (sb == 2) ? o2 : o3;
            int gq1 = (sb == 0) ? o1 : (sb == 1) ? o2 : (sb == 2) ? o3 : ncA;
            if (sb < sa) continue;
            int q0 = (a + 1 > gq0) ? a + 1 : gq0;
            if (q0 >= gq1) continue;
            float r = 0.0f;
            #pragma unroll 2
            for (int q = q0; q < gq1; q++) {
                float4 B4 = l4[q];
                float4 BB = lb[q];
                float dot = ax * B4.x + ay * B4.y + az * B4.z;
                float c   = dot * B4.w;                 // 0.95*cos(theta), |c|<=0.951
                float st  = sqrt_apx(fmaf(-c, c, 1.0f)); // sin >= 0.097
                float cosd = fmaf(c, cZ, st * sZ);      // cos(theta - ShfZ[t])
                float x    = fmaf(cosd, 0.5f, 0.5f);
                float f1;
                if (Z32) { float x2=x*x, x4=x2*x2, x8=x4*x4, x16=x8*x8; f1 = x16*x16; }
                else     { f1 = __powf(x, zeta); }
                float arg = fmaf(k2, BB.x, k1) + BB.z;  // nEtaA*(dmean-ShfA)^2 (log2-scaled)
                float f2  = ex2f(arg);
                r = fmaf(BB.y * f1, f2, r);             // fb*f1*f2
            }
            accA[(pbin0 + (sb - sa)) * 32 + lane] += fa2 * r;
        }
    }
}

__global__ __launch_bounds__(AWARPS*32) void aev_kernel(
    const float* __restrict__ coords,
    const float* __restrict__ etaR_p,
    const float* __restrict__ shfR_p,
    const float* __restrict__ etaA_p,
    const float* __restrict__ zeta_p,
    const float* __restrict__ shfA_p,
    const float* __restrict__ shfZ_p,
    const int*   __restrict__ species,
    float* __restrict__ out)
{
    __shared__ float s_cx[NATOMS], s_cy[NATOMS], s_cz[NATOMS];
    __shared__ int   s_sp[NATOMS];
    __shared__ float s_shfR[NSHFR], s_shfA[NSHFA];
    __shared__ float s_cosZ[NSHFZ], s_sinZ[NSHFZ];
    __shared__ float4 s_l4[NATOMS];          // vx, vy, vz, inv*sqrt(0.95)
    __shared__ float4 s_lb[NATOMS];          // 0.5d, fcA, nEtaA*(0.5d)^2, 0
    __shared__ float  s_acc[AWARPS][OUT_FEAT];
    __shared__ float  s_etaR, s_etaA, s_zeta;

    const int tid    = threadIdx.x;
    const int parity = tid >> 5;             // warp index = a-parity
    const int lane   = tid & 31;
    const int b      = blockIdx.x >> 5;      // 32 blocks per molecule
    const int i      = blockIdx.x & 31;      // this block's atom

    // ---- block-wide loads ----
    if (tid < NATOMS) {
        s_cx[tid] = coords[(b*NATOMS + tid)*3 + 0];
        s_cy[tid] = coords[(b*NATOMS + tid)*3 + 1];
        s_cz[tid] = coords[(b*NATOMS + tid)*3 + 2];
        s_sp[tid] = species[b*NATOMS + tid];
    } else if (tid < 32 + NSHFR) {
        s_shfR[tid-32] = shfR_p[tid-32];
    } else if (tid < 48 + NSHFA) {
        s_shfA[tid-48] = shfA_p[tid-48];
    } else if (tid < 55) {
        if (tid == 52) s_etaR = etaR_p[0];
        if (tid == 53) s_etaA = etaA_p[0];
        if (tid == 54) s_zeta = zeta_p[0];
    } else if (tid >= 56 && tid < 64) {
        float z = shfZ_p[tid-56];
        s_cosZ[tid-56] = cosf(z);
        s_sinZ[tid-56] = sinf(z);
    }
    for (int f = tid; f < AWARPS*OUT_FEAT; f += blockDim.x)
        (&s_acc[0][0])[f] = 0.0f;
    __syncthreads();

    const float etaA = s_etaA, zeta = s_zeta;
    const float nEtaR = -s_etaR * LOG2E;
    const float nEtaA = -etaA * LOG2E;
    const float PI_RCR = 3.14159265358979323846f / RCR;
    const float PI_RCA = 3.14159265358979323846f / RCA;

    // ---- candidate neighbor j = lane ----
    const float cix = s_cx[i], ciy = s_cy[i], ciz = s_cz[i];
    const bool  valid_i = (s_sp[i] >= 0);

    float vx = s_cx[lane] - cix;
    float vy = s_cy[lane] - ciy;
    float vz = s_cz[lane] - ciz;
    float d2 = vx*vx + vy*vy + vz*vz;
    float inv = rsqrt_apx(fmaxf(d2, 1e-24f));
    float d   = d2 * inv;
    int   spl = s_sp[lane];
    int   spc = min(max(spl, 0), NSP-1);
    bool  pair_ok = valid_i && (spl >= 0) && (lane != i);

    // ---- radial: 4 shifts per warp, staggered shared atomics ----
    if (pair_ok && d <= RCR) {
        float fcR  = fmaf(0.5f, __cosf(d * PI_RCR), 0.5f);
        float base = 0.25f * fcR;
        float* rad = &s_acc[parity][spc * NSHFR];
        int r0 = lane & 15;
        #pragma unroll
        for (int k = parity*4; k < parity*4 + 4; k++) {
            int r = (r0 + k) & 15;
            float e = d - s_shfR[r];
            atomicAdd(&rad[r], base * ex2f(nEtaR * (e * e)));
        }
    }

    // ---- angular: species-sorted compacted list (warp 0 writes it) ----
    bool isnb = pair_ok && (d <= RCA);
    unsigned ms[NSP];
    #pragma unroll
    for (int s = 0; s < NSP; s++)
        ms[s] = __ballot_sync(0xffffffffu, isnb && (spc == s));

    int o1 = __popc(ms[0]);
    int o2 = o1 + __popc(ms[1]);
    int o3 = o2 + __popc(ms[2]);
    int ncA = o3 + __popc(ms[3]);

    if (parity == 0 && isnb) {
        unsigned lt = (1u << lane) - 1u;
        int base = (spc == 0) ? 0 : (spc == 1) ? o1 : (spc == 2) ? o2 : o3;
        int pos = base + __popc(ms[spc] & lt);
        float fcA = fmaf(0.5f, __cosf(d * PI_RCA), 0.5f);
        float eb  = 0.5f * d;
        s_l4[pos] = make_float4(vx, vy, vz, inv * SQRT095);
        s_lb[pos] = make_float4(eb, fcA, nEtaA * eb * eb, 0.0f);
    }
    __syncthreads();

    const float shfA_l = s_shfA[lane >> 3];
    const float cZ = s_cosZ[lane & 7];
    const float sZ = s_sinZ[lane & 7];
    float* accA = &s_acc[parity][RAD_FEAT];

    if (fabsf(zeta - 32.0f) < 1e-4f)
        angular_loop<true >(s_l4, s_lb, o1, o2, o3, ncA, parity, lane,
                            shfA_l, cZ, sZ, nEtaA, zeta, accA);
    else
        angular_loop<false>(s_l4, s_lb, o1, o2, o3, ncA, parity, lane,
                            shfA_l, cZ, sZ, nEtaA, zeta, accA);
    __syncthreads();

    // ---- write: sum the 4 warp banks; each warp writes a quarter ----
    float* op = out + (size_t)(b*NATOMS + i) * OUT_FEAT;
    #pragma unroll
    for (int f = parity*96 + lane; f < parity*96 + 96; f += 32)
        op[f] = (s_acc[0][f] + s_acc[1][f]) + (s_acc[2][f] + s_acc[3][f]);
}

extern "C" void kernel_launch(void* const* d_in, const int* in_sizes, int n_in,
                              void* d_out, int out_size)
{
    const float* coords = (const float*)d_in[0];
    const float* etaR   = (const float*)d_in[1];
    const float* shfR   = (const float*)d_in[2];
    const float* etaA   = (const float*)d_in[3];
    const float* zeta   = (const float*)d_in[4];
    const float* shfA   = (const float*)d_in[5];
    const float* shfZ   = (const float*)d_in[6];
    const int*   spec   = (const int*)d_in[7];
    float* out = (float*)d_out;

    int B = in_sizes[0] / (NATOMS*3);
    dim3 grid(B * NATOMS);   // 1 atom per block, 4 warps per atom
    aev_kernel<<<grid, AWARPS*32>>>(coords, etaR, shfR, etaA, zeta, shfA, shfZ, spec, out);
}

// round 5
// speedup vs baseline: 3.5408x; 1.0816x over previous
#include <cuda_runtime.h>
#include <math.h>

#define RCR 5.2f
#define RCA 3.5f
#define NSP 4
#define NATOMS 32
#define NSHFR 16
#define NSHFA 4
#define NSHFZ 8
#define NPAIRBIN 10
#define RAD_FEAT (NSP*NSHFR)            /* 64  */
#define ANG_FEAT (NPAIRBIN*NSHFA*NSHFZ) /* 320 */
#define OUT_FEAT (RAD_FEAT+ANG_FEAT)    /* 384 */
#define AWARPS 4                         /* warps per atom */
#define LOG2E 1.4426950408889634f
#define SQRT095 0.97467943448089633f

__device__ __forceinline__ float ex2f(float x){ float y; asm("ex2.approx.ftz.f32 %0, %1;":"=f"(y):"f"(x)); return y; }
__device__ __forceinline__ float lg2f(float x){ float y; asm("lg2.approx.ftz.f32 %0, %1;":"=f"(y):"f"(x)); return y; }
__device__ __forceinline__ float sqrt_apx(float x){ float y; asm("sqrt.approx.ftz.f32 %0, %1;":"=f"(y):"f"(x)); return y; }
__device__ __forceinline__ float rsqrt_apx(float x){ float y; asm("rsqrt.approx.ftz.f32 %0, %1;":"=f"(y):"f"(x)); return y; }

// Records: l4 = (ux, uy, uz, 0.5*d) with u = v*inv(d)*sqrt(0.95)
//          lb = (fcA, nEtaA*(0.5d)^2 + log2(fcA))
// Lane owns angular feature f = p*8 + t (p = ShfA idx, t = ShfZ idx).
template<bool Z32>
__device__ __forceinline__ void angular_loop(
    const float4* __restrict__ l4, const float2* __restrict__ lb,
    int o1, int o2, int o3, int ncA, int w, int lane,
    float shfA_l, float cZ, float sZ, float nEtaA, float zeta,
    float* __restrict__ accA)
{
    const float nEtaA2 = 2.0f * nEtaA;
    const int nA = ncA - 1;
    // snake assignment: warp w takes a = 8s+w and 8s+7-w  (exactly equal work)
    for (int k = 0; ; k++) {
        int a = ((k >> 1) << 3) + ((k & 1) ? 7 - w : w);
        if (a >= nA) break;

        int sa = (a >= o3) ? 3 : (a >= o2) ? 2 : (a >= o1) ? 1 : 0;
        float4 A4 = l4[a];
        float2 A2 = lb[a];
        float ax = A4.x, ay = A4.y, az = A4.z;
        float ea  = A4.w - shfA_l;                       // 0.5*da - ShfA[p]
        float k1  = fmaf(nEtaA * ea, ea, Z32 ? -32.0f : 0.0f);
        float k2  = nEtaA2 * ea;
        float fa2 = 2.0f * A2.x;                         // 2*fcA(da)
        int pbin0 = sa * NSP - ((sa * (sa - 1)) >> 1);
        #pragma unroll
        for (int sb = 0; sb < NSP; sb++) {
            int gq0 = (sb == 0) ? 0  : (sb == 1) ? o1 : (sb == 2) ? o2 : o3;
            int gq1 = (sb == 0) ? o1 : (sb == 1) ? o2 : (sb == 2) ? o3 : ncA;
            if (sb < sa) continue;
            int q0 = (a + 1 > gq0) ? a + 1 : gq0;
            if (q0 >= gq1) continue;
            float r = 0.0f;
            #pragma unroll 2
            for (int q = q0; q < gq1; q++) {
                float4 B4 = l4[q];
                float2 B2 = lb[q];
                float c  = ax*B4.x + ay*B4.y + az*B4.z;   // 0.95*cos(theta)
                float st = sqrt_apx(fmaf(-c, c, 1.0f));   // 0.95*sin >= 0
                float t  = fmaf(st, sZ, 1.0f);
                float y  = fmaf(c, cZ, t);                // 1 + cos(theta - ShfZ[t])
                float f1;
                if (Z32) { float y2=y*y, y4=y2*y2, y8=y4*y4, y16=y8*y8; f1 = y16*y16; }
                else     { f1 = __powf(0.5f * y, zeta); }
                float arg = fmaf(k2, B4.w, k1) + B2.y;    // Gaussian + log2(fcb) (+ -32)
                r = fmaf(f1, ex2f(arg), r);
            }
            accA[(pbin0 + (sb - sa)) * 32 + lane] += fa2 * r;
        }
    }
}

__global__ __launch_bounds__(AWARPS*32) void aev_kernel(
    const float* __restrict__ coords,
    const float* __restrict__ etaR_p,
    const float* __restrict__ shfR_p,
    const float* __restrict__ etaA_p,
    const float* __restrict__ zeta_p,
    const float* __restrict__ shfA_p,
    const float* __restrict__ shfZ_p,
    const int*   __restrict__ species,
    float* __restrict__ out)
{
    __shared__ float s_cx[NATOMS], s_cy[NATOMS], s_cz[NATOMS];
    __shared__ int   s_sp[NATOMS];
    __shared__ float s_shfR[NSHFR], s_shfA[NSHFA];
    __shared__ float s_cosZ[NSHFZ], s_sinZ[NSHFZ];
    __shared__ float4 s_l4[NATOMS];
    __shared__ float2 s_lb[NATOMS];
    __shared__ float  s_acc[AWARPS][OUT_FEAT];
    __shared__ float  s_etaR, s_etaA, s_zeta;

    const int tid  = threadIdx.x;
    const int w    = tid >> 5;               // warp index
    const int lane = tid & 31;
    const int b    = blockIdx.x >> 5;        // 32 blocks per molecule
    const int i    = blockIdx.x & 31;        // this block's atom

    // ---- block-wide loads ----
    if (tid < NATOMS) {
        s_cx[tid] = coords[(b*NATOMS + tid)*3 + 0];
        s_cy[tid] = coords[(b*NATOMS + tid)*3 + 1];
        s_cz[tid] = coords[(b*NATOMS + tid)*3 + 2];
        s_sp[tid] = species[b*NATOMS + tid];
    } else if (tid < 32 + NSHFR) {
        s_shfR[tid-32] = shfR_p[tid-32];
    } else if (tid < 48 + NSHFA) {
        s_shfA[tid-48] = shfA_p[tid-48];
    } else if (tid < 55) {
        if (tid == 52) s_etaR = etaR_p[0];
        if (tid == 53) s_etaA = etaA_p[0];
        if (tid == 54) s_zeta = zeta_p[0];
    } else if (tid >= 56 && tid < 64) {
        float z = shfZ_p[tid-56];
        s_cosZ[tid-56] = cosf(z);
        s_sinZ[tid-56] = sinf(z);
    }
    for (int f = tid; f < AWARPS*OUT_FEAT; f += blockDim.x)
        (&s_acc[0][0])[f] = 0.0f;
    __syncthreads();

    const float zeta = s_zeta;
    const float nEtaR = -s_etaR * LOG2E;
    const float nEtaA = -s_etaA * LOG2E;
    const float PI_RCR = 3.14159265358979323846f / RCR;
    const float PI_RCA = 3.14159265358979323846f / RCA;

    // ---- candidate neighbor j = lane ----
    const float cix = s_cx[i], ciy = s_cy[i], ciz = s_cz[i];
    const bool  valid_i = (s_sp[i] >= 0);

    float vx = s_cx[lane] - cix;
    float vy = s_cy[lane] - ciy;
    float vz = s_cz[lane] - ciz;
    float d2 = vx*vx + vy*vy + vz*vz;
    float inv = rsqrt_apx(fmaxf(d2, 1e-24f));
    float d   = d2 * inv;
    int   spl = s_sp[lane];
    int   spc = min(max(spl, 0), NSP-1);
    bool  pair_ok = valid_i && (spl >= 0) && (lane != i);

    // ---- radial: 4 shifts per warp, staggered shared atomics ----
    if (pair_ok && d <= RCR) {
        float fcR  = fmaf(0.5f, __cosf(d * PI_RCR), 0.5f);
        float base = 0.25f * fcR;
        float* rad = &s_acc[w][spc * NSHFR];
        int r0 = lane & 15;
        #pragma unroll
        for (int k = w*4; k < w*4 + 4; k++) {
            int r = (r0 + k) & 15;
            float e = d - s_shfR[r];
            atomicAdd(&rad[r], base * ex2f(nEtaR * (e * e)));
        }
    }

    // ---- angular: species-sorted compacted list (warp 0 writes it) ----
    bool isnb = pair_ok && (d <= RCA);
    unsigned ms[NSP];
    #pragma unroll
    for (int s = 0; s < NSP; s++)
        ms[s] = __ballot_sync(0xffffffffu, isnb && (spc == s));

    int o1 = __popc(ms[0]);
    int o2 = o1 + __popc(ms[1]);
    int o3 = o2 + __popc(ms[2]);
    int ncA = o3 + __popc(ms[3]);

    if (w == 0 && isnb) {
        unsigned lt = (1u << lane) - 1u;
        int base = (spc == 0) ? 0 : (spc == 1) ? o1 : (spc == 2) ? o2 : o3;
        int pos = base + __popc(ms[spc] & lt);
        float fcA = fmaf(0.5f, __cosf(d * PI_RCA), 0.5f);
        float eb  = 0.5f * d;
        float us  = inv * SQRT095;
        s_l4[pos] = make_float4(vx*us, vy*us, vz*us, eb);
        s_lb[pos] = make_float2(fcA, fmaf(nEtaA * eb, eb, lg2f(fcA)));
    }
    __syncthreads();

    const float shfA_l = s_shfA[lane >> 3];
    const float cZ = s_cosZ[lane & 7];
    const float sZ = s_sinZ[lane & 7];
    float* accA = &s_acc[w][RAD_FEAT];

    if (fabsf(zeta - 32.0f) < 1e-4f)
        angular_loop<true >(s_l4, s_lb, o1, o2, o3, ncA, w, lane,
                            shfA_l, cZ, sZ, nEtaA, zeta, accA);
    else
        angular_loop<false>(s_l4, s_lb, o1, o2, o3, ncA, w, lane,
                            shfA_l, cZ, sZ, nEtaA, zeta, accA);
    __syncthreads();

    // ---- write: sum the 4 warp banks; each warp writes a quarter ----
    float* op = out + (size_t)(b*NATOMS + i) * OUT_FEAT;
    #pragma unroll
    for (int f = w*96 + lane; f < w*96 + 96; f += 32)
        op[f] = (s_acc[0][f] + s_acc[1][f]) + (s_acc[2][f] + s_acc[3][f]);
}

extern "C" void kernel_launch(void* const* d_in, const int* in_sizes, int n_in,
                              void* d_out, int out_size)
{
    const float* coords = (const float*)d_in[0];
    const float* etaR   = (const float*)d_in[1];
    const float* shfR   = (const float*)d_in[2];
    const float* etaA   = (const float*)d_in[3];
    const float* zeta   = (const float*)d_in[4];
    const float* shfA   = (const float*)d_in[5];
    const float* shfZ   = (const float*)d_in[6];
    const int*   spec   = (const int*)d_in[7];
    float* out = (float*)d_out;

    int B = in_sizes[0] / (NATOMS*3);
    dim3 grid(B * NATOMS);   // 1 atom per block, 4 warps per atom
    aev_kernel<<<grid, AWARPS*32>>>(coords, etaR, shfR, etaA, zeta, shfA, shfZ, spec, out);
}

// round 6
// speedup vs baseline: 3.8184x; 1.0784x over previous
#include <cuda_runtime.h>
#include <math.h>

#define RCR 5.2f
#define RCA 3.5f
#define NSP 4
#define NATOMS 32
#define NSHFR 16
#define NSHFA 4
#define NSHFZ 8
#define NPAIRBIN 10
#define RAD_FEAT (NSP*NSHFR)            /* 64  */
#define ANG_FEAT (NPAIRBIN*NSHFA*NSHFZ) /* 320 */
#define OUT_FEAT (RAD_FEAT+ANG_FEAT)    /* 384 */
#define AWARPS 4
#define MAXP 496                         /* max pairs: 31*30/2 = 465 */
#define LOG2E 1.4426950408889634f
#define SQRT095 0.97467943448089633f

__device__ __forceinline__ float ex2f(float x){ float y; asm("ex2.approx.ftz.f32 %0, %1;":"=f"(y):"f"(x)); return y; }
__device__ __forceinline__ float lg2f(float x){ float y; asm("lg2.approx.ftz.f32 %0, %1;":"=f"(y):"f"(x)); return y; }
__device__ __forceinline__ float sqrt_apx(float x){ float y; asm("sqrt.approx.ftz.f32 %0, %1;":"=f"(y):"f"(x)); return y; }
__device__ __forceinline__ float rsqrt_apx(float x){ float y; asm("rsqrt.approx.ftz.f32 %0, %1;":"=f"(y):"f"(x)); return y; }

// Broadcast phase: pair record R = (c, st, A, B); value = y^32 * ex2(arg)  (Z32)
// arg = A + B*shfA_l + Cl,  Cl = nEtaA*shfA_l^2.
template<bool Z32>
__device__ __forceinline__ void pair_loop(
    const float4* __restrict__ p4, const int* __restrict__ pb,
    int g0, int g1, int lane,
    float shfA_l, float cZ, float sZ, float Cl, float zeta,
    float* __restrict__ accA)
{
    if (g0 >= g1) return;
    int cur = pb[g0];
    float r = 0.0f;
    #pragma unroll 4
    for (int g = g0; g < g1; g++) {
        float4 R = p4[g];          // broadcast LDS.128
        int pbn = pb[g];           // broadcast LDS.32 (warp-uniform)
        if (pbn != cur) { accA[cur*32 + lane] += r; r = 0.0f; cur = pbn; }
        float t = fmaf(R.y, sZ, 1.0f);
        float y = fmaf(R.x, cZ, t);          // 1 + cos(theta - ShfZ[t])
        float f1;
        if (Z32) { float y2=y*y, y4=y2*y2, y8=y4*y4, y16=y8*y8; f1 = y16*y16; }
        else     { f1 = __powf(0.5f*y, zeta); }
        float arg = fmaf(R.w, shfA_l, R.z) + Cl;
        r = fmaf(f1, ex2f(arg), r);
    }
    accA[cur*32 + lane] += r;
}

__global__ __launch_bounds__(AWARPS*32) void aev_kernel(
    const float* __restrict__ coords,
    const float* __restrict__ etaR_p,
    const float* __restrict__ shfR_p,
    const float* __restrict__ etaA_p,
    const float* __restrict__ zeta_p,
    const float* __restrict__ shfA_p,
    const float* __restrict__ shfZ_p,
    const int*   __restrict__ species,
    float* __restrict__ out)
{
    __shared__ float s_cx[NATOMS], s_cy[NATOMS], s_cz[NATOMS];
    __shared__ int   s_sp[NATOMS];
    __shared__ float s_shfR[NSHFR], s_shfA[NSHFA];
    __shared__ float s_cosZ[NSHFZ], s_sinZ[NSHFZ];
    __shared__ float4 s_n4[NATOMS];          // ux,uy,uz (x sqrt095), 0.5*d
    __shared__ float  s_nlg[NATOMS];         // lg2(fcA)
    __shared__ int    s_nsp[NATOMS];         // species
    __shared__ float4 s_p4[MAXP];            // c, st, A, B
    __shared__ int    s_pb[MAXP];            // pbin
    __shared__ float  s_acc[AWARPS][OUT_FEAT];
    __shared__ float  s_etaR, s_etaA, s_zeta;

    const int tid  = threadIdx.x;
    const int w    = tid >> 5;
    const int lane = tid & 31;
    const int b    = blockIdx.x >> 5;        // 32 blocks per molecule
    const int i    = blockIdx.x & 31;        // this block's atom

    // ---- block-wide loads ----
    if (tid < NATOMS) {
        s_cx[tid] = coords[(b*NATOMS + tid)*3 + 0];
        s_cy[tid] = coords[(b*NATOMS + tid)*3 + 1];
        s_cz[tid] = coords[(b*NATOMS + tid)*3 + 2];
        s_sp[tid] = species[b*NATOMS + tid];
    } else if (tid < 32 + NSHFR) {
        s_shfR[tid-32] = shfR_p[tid-32];
    } else if (tid < 48 + NSHFA) {
        s_shfA[tid-48] = shfA_p[tid-48];
    } else if (tid < 55) {
        if (tid == 52) s_etaR = etaR_p[0];
        if (tid == 53) s_etaA = etaA_p[0];
        if (tid == 54) s_zeta = zeta_p[0];
    } else if (tid >= 56 && tid < 64) {
        float z = shfZ_p[tid-56];
        s_cosZ[tid-56] = cosf(z);
        s_sinZ[tid-56] = sinf(z);
    }
    for (int f = tid; f < AWARPS*OUT_FEAT; f += blockDim.x)
        (&s_acc[0][0])[f] = 0.0f;
    __syncthreads();

    const float zeta = s_zeta;
    const float nEtaR = -s_etaR * LOG2E;
    const float nEtaA = -s_etaA * LOG2E;
    const bool  z32   = (fabsf(zeta - 32.0f) < 1e-4f);
    const float PI_RCR = 3.14159265358979323846f / RCR;
    const float PI_RCA = 3.14159265358979323846f / RCA;

    // ---- candidate neighbor j = lane ----
    const float cix = s_cx[i], ciy = s_cy[i], ciz = s_cz[i];
    const bool  valid_i = (s_sp[i] >= 0);

    float vx = s_cx[lane] - cix;
    float vy = s_cy[lane] - ciy;
    float vz = s_cz[lane] - ciz;
    float d2 = vx*vx + vy*vy + vz*vz;
    float inv = rsqrt_apx(fmaxf(d2, 1e-24f));
    float d   = d2 * inv;
    int   spl = s_sp[lane];
    int   spc = min(max(spl, 0), NSP-1);
    bool  pair_ok = valid_i && (spl >= 0) && (lane != i);

    // ---- radial: 4 shifts per warp, staggered shared atomics ----
    if (pair_ok && d <= RCR) {
        float fcR  = fmaf(0.5f, __cosf(d * PI_RCR), 0.5f);
        float base = 0.25f * fcR;
        float* rad = &s_acc[w][spc * NSHFR];
        int r0 = lane & 15;
        #pragma unroll
        for (int k = w*4; k < w*4 + 4; k++) {
            int r = (r0 + k) & 15;
            float e = d - s_shfR[r];
            atomicAdd(&rad[r], base * ex2f(nEtaR * (e * e)));
        }
    }

    // ---- neighbor list: species-sorted compaction (warp 0 writes it) ----
    bool isnb = pair_ok && (d <= RCA);
    unsigned ms[NSP];
    #pragma unroll
    for (int s = 0; s < NSP; s++)
        ms[s] = __ballot_sync(0xffffffffu, isnb && (spc == s));

    int o1 = __popc(ms[0]);
    int o2 = o1 + __popc(ms[1]);
    int o3 = o2 + __popc(ms[2]);
    int ncA = o3 + __popc(ms[3]);

    if (w == 0 && isnb) {
        unsigned lt = (1u << lane) - 1u;
        int base = (spc == 0) ? 0 : (spc == 1) ? o1 : (spc == 2) ? o2 : o3;
        int pos = base + __popc(ms[spc] & lt);
        float fcA = fmaf(0.5f, __cosf(d * PI_RCA), 0.5f);
        float us  = inv * SQRT095;
        s_n4[pos]  = make_float4(vx*us, vy*us, vz*us, 0.5f*d);
        s_nlg[pos] = lg2f(fcA);
        s_nsp[pos] = spc;
    }
    __syncthreads();

    // ---- geometry phase: one lane per pair, flat triangular enumeration ----
    const int P = (ncA * (ncA - 1)) >> 1;
    const float zoff = z32 ? -31.0f : 1.0f;   // lg2(2*fa*fb) "+1", minus 32 if folded pow
    const float nEtaA2m = -2.0f * nEtaA;
    {
        const float n1 = (float)(2*ncA - 1);
        for (int g = tid; g < P; g += AWARPS*32) {
            float sdisc = sqrtf(fmaf(n1, n1, (float)(-8*g)));
            int a = (int)(0.5f * (n1 - sdisc));
            a = max(a, 0);
            // fixup against off(a) = a*(ncA-1) - a(a-1)/2
            while (a*(ncA-1) - ((a*(a-1))>>1) > g) a--;
            while ((a+1)*(ncA-1) - (((a+1)*a)>>1) <= g) a++;
            int q = g - (a*(ncA-1) - ((a*(a-1))>>1)) + a + 1;

            float4 A4 = s_n4[a];
            float4 B4 = s_n4[q];
            float c  = A4.x*B4.x + A4.y*B4.y + A4.z*B4.z;   // 0.95*cos(theta)
            float st = sqrt_apx(fmaf(-c, c, 1.0f));          // 0.95*sin >= 0
            float dm = A4.w + B4.w;                          // dmean
            float lg = s_nlg[a] + s_nlg[q] + zoff;
            float Ar = fmaf(nEtaA * dm, dm, lg);
            float Br = nEtaA2m * dm;
            int sa = s_nsp[a], sq = s_nsp[q];
            int lo = min(sa, sq), hi = max(sa, sq);
            int pbin = lo*NSP - ((lo*(lo-1))>>1) + (hi - lo);
            s_p4[g] = make_float4(c, st, Ar, Br);
            s_pb[g] = pbin;
        }
    }
    __syncthreads();

    // ---- broadcast phase: warp w sweeps its quarter of the pair array ----
    const float shfA_l = s_shfA[lane >> 3];
    const float cZ = s_cosZ[lane & 7];
    const float sZ = s_sinZ[lane & 7];
    const float Cl = nEtaA * shfA_l * shfA_l;
    float* accA = &s_acc[w][RAD_FEAT];

    int g0 = (P * w) >> 2;
    int g1 = (P * (w+1)) >> 2;
    if (z32) pair_loop<true >(s_p4, s_pb, g0, g1, lane, shfA_l, cZ, sZ, Cl, zeta, accA);
    else     pair_loop<false>(s_p4, s_pb, g0, g1, lane, shfA_l, cZ, sZ, Cl, zeta, accA);
    __syncthreads();

    // ---- write: sum the 4 warp banks; each warp writes a quarter ----
    float* op = out + (size_t)(b*NATOMS + i) * OUT_FEAT;
    #pragma unroll
    for (int f = w*96 + lane; f < w*96 + 96; f += 32)
        op[f] = (s_acc[0][f] + s_acc[1][f]) + (s_acc[2][f] + s_acc[3][f]);
}

extern "C" void kernel_launch(void* const* d_in, const int* in_sizes, int n_in,
                              void* d_out, int out_size)
{
    const float* coords = (const float*)d_in[0];
    const float* etaR   = (const float*)d_in[1];
    const float* shfR   = (const float*)d_in[2];
    const float* etaA   = (const float*)d_in[3];
    const float* zeta   = (const float*)d_in[4];
    const float* shfA   = (const float*)d_in[5];
    const float* shfZ   = (const float*)d_in[6];
    const int*   spec   = (const int*)d_in[7];
    float* out = (float*)d_out;

    int B = in_sizes[0] / (NATOMS*3);
    dim3 grid(B * NATOMS);   // 1 atom per block, 4 warps
    aev_kernel<<<grid, AWARPS*32>>>(coords, etaR, shfR, etaA, zeta, shfA, shfZ, spec, out);
}